// round 1
// baseline (speedup 1.0000x reference)
#include <cuda_runtime.h>
#include <math.h>

// ---------------- problem constants ----------------
#define B_   8
#define HH_  56
#define WW_  56
#define N_   (HH_*WW_)          // 3136
#define C_   512
#define NH_  16
#define HD_  32
#define WS_  7
#define WS2_ 49
#define HID_ 2048
#define TOK_ (B_*N_)            // 25088
#define THREEC_ (3*C_)          // 1536

// ---------------- scratch (device globals; no allocation allowed) ----------------
static __device__ float g_h  [(size_t)TOK_*C_];      // LN1 out, reused for LN2 out
static __device__ float g_qkv[(size_t)TOK_*THREEC_]; // qkv
static __device__ float g_x1 [(size_t)TOK_*C_];      // x + attn
static __device__ float g_h2 [(size_t)TOK_*HID_];    // fc1 out
static __device__ float g_h3 [(size_t)TOK_*HID_];    // dwconv+gelu out

// ---------------- block reduce ----------------
__inline__ __device__ float blockReduceSum256(float val) {
    __shared__ float sh[8];
    __shared__ float res;
    int lane = threadIdx.x & 31, wid = threadIdx.x >> 5;
    #pragma unroll
    for (int o = 16; o > 0; o >>= 1) val += __shfl_down_sync(0xffffffffu, val, o);
    if (lane == 0) sh[wid] = val;
    __syncthreads();
    if (wid == 0) {
        float v = (lane < 8) ? sh[lane] : 0.0f;
        #pragma unroll
        for (int o = 4; o > 0; o >>= 1) v += __shfl_down_sync(0xffffffffu, v, o);
        if (lane == 0) res = v;
    }
    __syncthreads();
    return res;
}

// ---------------- LayerNorm: one block (256 thr) per token row of 512 ----------------
__global__ __launch_bounds__(256)
void ln_kernel(const float* __restrict__ x, const float* __restrict__ g,
               const float* __restrict__ b, float* __restrict__ out) {
    long row = blockIdx.x;
    const float* xr = x + row * C_;
    float v0 = xr[threadIdx.x];
    float v1 = xr[threadIdx.x + 256];
    float mu = blockReduceSum256(v0 + v1) * (1.0f / C_);
    float d0 = v0 - mu, d1 = v1 - mu;
    float var = blockReduceSum256(d0 * d0 + d1 * d1) * (1.0f / C_);
    float inv = rsqrtf(var + 1e-5f);
    float* o = out + row * C_;
    o[threadIdx.x]       = d0 * inv * g[threadIdx.x]       + b[threadIdx.x];
    o[threadIdx.x + 256] = d1 * inv * g[threadIdx.x + 256] + b[threadIdx.x + 256];
}

// ---------------- SGEMM: out[M,N] = A[M,K] @ B[N,K]^T + bias[N] (+res[M,N]) ----------
// 64x64 tile, BK=16, 256 threads, 4x4 micro-tile. M,N div by 64; K div by 16.
#define BM 64
#define BN 64
#define BK 16
__global__ __launch_bounds__(256)
void gemm_kernel(const float* __restrict__ A, const float* __restrict__ Bm,
                 const float* __restrict__ bias, const float* __restrict__ res,
                 float* __restrict__ out, int M, int N, int K) {
    __shared__ float As[BK][BM];
    __shared__ float Bs[BK][BN];
    const int tid = threadIdx.x;
    const int tx = tid & 15, ty = tid >> 4;
    const int m0 = blockIdx.y * BM, n0 = blockIdx.x * BN;
    const int lr = tid >> 2;            // 0..63
    const int lc = (tid & 3) * 4;       // 0,4,8,12

    float acc[4][4];
    #pragma unroll
    for (int i = 0; i < 4; ++i)
        #pragma unroll
        for (int j = 0; j < 4; ++j) acc[i][j] = 0.0f;

    for (int k0 = 0; k0 < K; k0 += BK) {
        float4 av = *(const float4*)(A + (long)(m0 + lr) * K + k0 + lc);
        float4 bv = *(const float4*)(Bm + (long)(n0 + lr) * K + k0 + lc);
        As[lc + 0][lr] = av.x; As[lc + 1][lr] = av.y; As[lc + 2][lr] = av.z; As[lc + 3][lr] = av.w;
        Bs[lc + 0][lr] = bv.x; Bs[lc + 1][lr] = bv.y; Bs[lc + 2][lr] = bv.z; Bs[lc + 3][lr] = bv.w;
        __syncthreads();
        #pragma unroll
        for (int kk = 0; kk < BK; ++kk) {
            float4 a = ((const float4*)As[kk])[ty];
            float4 b = ((const float4*)Bs[kk])[tx];
            float aa[4] = {a.x, a.y, a.z, a.w};
            float bb[4] = {b.x, b.y, b.z, b.w};
            #pragma unroll
            for (int i = 0; i < 4; ++i)
                #pragma unroll
                for (int j = 0; j < 4; ++j) acc[i][j] = fmaf(aa[i], bb[j], acc[i][j]);
        }
        __syncthreads();
    }
    #pragma unroll
    for (int i = 0; i < 4; ++i) {
        int m = m0 + ty * 4 + i;
        #pragma unroll
        for (int j = 0; j < 4; ++j) {
            int n = n0 + tx * 4 + j;
            float v = acc[i][j] + bias[n];
            if (res) v += res[(long)m * N + n];
            out[(long)m * N + n] = v;
        }
    }
}

// ---------------- Windowed attention, one block per (window, head) ------------------
// qkv layout: [B, N, 3, NH, HD] flattened over last dims (3C = 1536).
__global__ __launch_bounds__(256)
void attn_kernel(const float* __restrict__ qkv, const float* __restrict__ rpb,
                 const float* __restrict__ x, float* __restrict__ x1) {
    const int head = blockIdx.x & 15;
    const int win  = blockIdx.x >> 4;
    const int b    = win >> 6;
    const int wi   = (win >> 3) & 7;
    const int wj   = win & 7;
    const int tid  = threadIdx.x;

    __shared__ float q[WS2_][HD_];
    __shared__ float k[WS2_][HD_];
    __shared__ float v[WS2_][HD_];
    __shared__ float s[WS2_][WS2_ + 1];

    for (int idx = tid; idx < WS2_ * HD_; idx += 256) {
        int p = idx >> 5, d = idx & 31;
        int token = (wi * 7 + p / 7) * 56 + (wj * 7 + p % 7);
        long base = ((long)b * N_ + token) * THREEC_ + head * HD_ + d;
        q[p][d] = qkv[base];
        k[p][d] = qkv[base + C_];
        v[p][d] = qkv[base + 2 * C_];
    }
    __syncthreads();

    const float scale = 0.17677669529663687f; // 1/sqrt(32)
    for (int idx = tid; idx < WS2_ * WS2_; idx += 256) {
        int i = idx / WS2_, j = idx - i * WS2_;
        float acc = 0.0f;
        #pragma unroll
        for (int d = 0; d < HD_; ++d) acc = fmaf(q[i][d], k[j][d], acc);
        int dpi = (i / 7) - (j / 7) + 6;
        int dpj = (i % 7) - (j % 7) + 6;
        s[i][j] = acc * scale + rpb[(dpi * 13 + dpj) * NH_ + head];
    }
    __syncthreads();

    if (tid < WS2_) {
        float mx = -1e30f;
        #pragma unroll
        for (int j = 0; j < WS2_; ++j) mx = fmaxf(mx, s[tid][j]);
        float sum = 0.0f;
        #pragma unroll
        for (int j = 0; j < WS2_; ++j) { float e = __expf(s[tid][j] - mx); s[tid][j] = e; sum += e; }
        float inv = 1.0f / sum;
        #pragma unroll
        for (int j = 0; j < WS2_; ++j) s[tid][j] *= inv;
    }
    __syncthreads();

    for (int idx = tid; idx < WS2_ * HD_; idx += 256) {
        int i = idx >> 5, d = idx & 31;
        float acc = 0.0f;
        #pragma unroll
        for (int j = 0; j < WS2_; ++j) acc = fmaf(s[i][j], v[j][d], acc);
        int token = (wi * 7 + i / 7) * 56 + (wj * 7 + i % 7);
        long o = ((long)b * N_ + token) * C_ + head * HD_ + d;
        x1[o] = x[o] + acc;
    }
}

// ---------------- depthwise 3x3 (NHWC) + bias + exact GELU --------------------------
__global__ __launch_bounds__(256)
void dwconv_gelu_kernel(const float* __restrict__ h2, const float* __restrict__ w,
                        const float* __restrict__ bias, float* __restrict__ out) {
    __shared__ float ws[256 * 9];
    long idx = (long)blockIdx.x * 256 + threadIdx.x;
    int c = (int)(idx & (HID_ - 1));
    int c0 = (int)((blockIdx.x * 256L) & (HID_ - 1)); // block covers [c0, c0+256)
    #pragma unroll
    for (int t = 0; t < 9; ++t) ws[threadIdx.x * 9 + t] = w[(c0 + threadIdx.x) * 9 + t];
    __syncthreads();

    long sp = idx >> 11;           // / HID_
    int wcol = (int)(sp % 56);
    long t2 = sp / 56;
    int hrow = (int)(t2 % 56);
    int bb = (int)(t2 / 56);
    const float* wt = &ws[(c - c0) * 9];

    float acc = bias[c];
    #pragma unroll
    for (int dy = 0; dy < 3; ++dy) {
        int hh = hrow + dy - 1;
        if (hh < 0 || hh >= 56) continue;
        #pragma unroll
        for (int dx = 0; dx < 3; ++dx) {
            int ww = wcol + dx - 1;
            if (ww < 0 || ww >= 56) continue;
            acc = fmaf(h2[(((long)bb * 56 + hh) * 56 + ww) * HID_ + c], wt[dy * 3 + dx], acc);
        }
    }
    out[idx] = 0.5f * acc * (1.0f + erff(acc * 0.70710678118654752f));
}

// ---------------- launch ----------------
extern "C" void kernel_launch(void* const* d_in, const int* in_sizes, int n_in,
                              void* d_out, int out_size) {
    const float* x       = (const float*)d_in[0];
    // d_in[1]=H, d_in[2]=W (constants 56, ignored)
    const float* norm1_g = (const float*)d_in[3];
    const float* norm1_b = (const float*)d_in[4];
    const float* norm2_g = (const float*)d_in[5];
    const float* norm2_b = (const float*)d_in[6];
    const float* qkv_w   = (const float*)d_in[7];
    const float* qkv_b   = (const float*)d_in[8];
    const float* rpb     = (const float*)d_in[9];
    const float* fc1_w   = (const float*)d_in[10];
    const float* fc1_b   = (const float*)d_in[11];
    const float* dw_w    = (const float*)d_in[12];
    const float* dw_b    = (const float*)d_in[13];
    const float* fc2_w   = (const float*)d_in[14];
    const float* fc2_b   = (const float*)d_in[15];
    float* out = (float*)d_out;

    float *p_h, *p_qkv, *p_x1, *p_h2, *p_h3;
    cudaGetSymbolAddress((void**)&p_h,   g_h);
    cudaGetSymbolAddress((void**)&p_qkv, g_qkv);
    cudaGetSymbolAddress((void**)&p_x1,  g_x1);
    cudaGetSymbolAddress((void**)&p_h2,  g_h2);
    cudaGetSymbolAddress((void**)&p_h3,  g_h3);

    // 1) LN1
    ln_kernel<<<TOK_, 256>>>(x, norm1_g, norm1_b, p_h);
    // 2) QKV GEMM: [25088,512] x [1536,512]^T
    gemm_kernel<<<dim3(THREEC_ / BN, TOK_ / BM), 256>>>(p_h, qkv_w, qkv_b, nullptr, p_qkv,
                                                        TOK_, THREEC_, C_);
    // 3) windowed attention + residual -> x1
    attn_kernel<<<B_ * 64 * NH_, 256>>>(p_qkv, rpb, x, p_x1);
    // 4) LN2
    ln_kernel<<<TOK_, 256>>>(p_x1, norm2_g, norm2_b, p_h);
    // 5) fc1 GEMM: [25088,512] x [2048,512]^T
    gemm_kernel<<<dim3(HID_ / BN, TOK_ / BM), 256>>>(p_h, fc1_w, fc1_b, nullptr, p_h2,
                                                     TOK_, HID_, C_);
    // 6) depthwise conv + bias + GELU
    dwconv_gelu_kernel<<<(unsigned)(((long)TOK_ * HID_) / 256), 256>>>(p_h2, dw_w, dw_b, p_h3);
    // 7) fc2 GEMM + bias + residual(x1) -> out
    gemm_kernel<<<dim3(C_ / BN, TOK_ / BM), 256>>>(p_h3, fc2_w, fc2_b, p_x1, out,
                                                   TOK_, C_, HID_);
}

// round 2
// speedup vs baseline: 2.3149x; 2.3149x over previous
#include <cuda_runtime.h>
#include <math.h>

// ---------------- problem constants ----------------
#define B_   8
#define HH_  56
#define WW_  56
#define N_   (HH_*WW_)          // 3136
#define C_   512
#define NH_  16
#define HD_  32
#define WS_  7
#define WS2_ 49
#define HID_ 2048
#define TOK_ (B_*N_)            // 25088
#define THREEC_ (3*C_)          // 1536

// ---------------- scratch (device globals; no allocation allowed) ----------------
static __device__ float g_h  [(size_t)TOK_*C_];      // LN1 out, reused for LN2 out
static __device__ float g_qkv[(size_t)TOK_*THREEC_]; // qkv
static __device__ float g_x1 [(size_t)TOK_*C_];      // x + attn
static __device__ float g_h2 [(size_t)TOK_*HID_];    // fc1 out
static __device__ float g_h3 [(size_t)TOK_*HID_];    // dwconv+gelu out

// ---------------- block reduce ----------------
__inline__ __device__ float blockReduceSum256(float val) {
    __shared__ float sh[8];
    __shared__ float res;
    int lane = threadIdx.x & 31, wid = threadIdx.x >> 5;
    #pragma unroll
    for (int o = 16; o > 0; o >>= 1) val += __shfl_down_sync(0xffffffffu, val, o);
    if (lane == 0) sh[wid] = val;
    __syncthreads();
    if (wid == 0) {
        float v = (lane < 8) ? sh[lane] : 0.0f;
        #pragma unroll
        for (int o = 4; o > 0; o >>= 1) v += __shfl_down_sync(0xffffffffu, v, o);
        if (lane == 0) res = v;
    }
    __syncthreads();
    return res;
}

// ---------------- LayerNorm ----------------
__global__ __launch_bounds__(256)
void ln_kernel(const float* __restrict__ x, const float* __restrict__ g,
               const float* __restrict__ b, float* __restrict__ out) {
    long row = blockIdx.x;
    const float* xr = x + row * C_;
    float v0 = xr[threadIdx.x];
    float v1 = xr[threadIdx.x + 256];
    float mu = blockReduceSum256(v0 + v1) * (1.0f / C_);
    float d0 = v0 - mu, d1 = v1 - mu;
    float var = blockReduceSum256(d0 * d0 + d1 * d1) * (1.0f / C_);
    float inv = rsqrtf(var + 1e-5f);
    float* o = out + row * C_;
    o[threadIdx.x]       = d0 * inv * g[threadIdx.x]       + b[threadIdx.x];
    o[threadIdx.x + 256] = d1 * inv * g[threadIdx.x + 256] + b[threadIdx.x + 256];
}

// ---------------- TF32 tensor-core GEMM ----------------
// out[M,N] = A[M,K] @ B[N,K]^T + bias[N] (+res). M%128==0, N%128==0, K%32==0.
#define GBM 128
#define GBN 128
#define GBK 32
#define PAD 36   // row stride in floats; 36%32==4 -> frag loads conflict-free

__device__ __forceinline__ float tf32r(float x) {
    float r; asm("cvt.rna.tf32.f32 %0, %1;" : "=f"(r) : "f"(x)); return r;
}

__device__ __forceinline__ void mma_tf32(float* c, const float* a, const float* b) {
    asm volatile(
        "mma.sync.aligned.m16n8k8.row.col.f32.tf32.tf32.f32 "
        "{%0,%1,%2,%3}, {%4,%5,%6,%7}, {%8,%9}, {%0,%1,%2,%3};"
        : "+f"(c[0]), "+f"(c[1]), "+f"(c[2]), "+f"(c[3])
        : "r"(__float_as_uint(a[0])), "r"(__float_as_uint(a[1])),
          "r"(__float_as_uint(a[2])), "r"(__float_as_uint(a[3])),
          "r"(__float_as_uint(b[0])), "r"(__float_as_uint(b[1])));
}

__global__ __launch_bounds__(256)
void gemm_tf32_kernel(const float* __restrict__ A, const float* __restrict__ Bm,
                      const float* __restrict__ bias, const float* __restrict__ res,
                      float* __restrict__ out, int M, int N, int K) {
    __shared__ float As[GBM * PAD];
    __shared__ float Bs[GBN * PAD];
    const int tid = threadIdx.x;
    const int lane = tid & 31, wid = tid >> 5;
    const int wm = wid & 3, wn = wid >> 2;      // 4 warps along M, 2 along N
    const int ly = lane >> 2, lc = lane & 3;
    const int m0 = blockIdx.y * GBM, n0 = blockIdx.x * GBN;

    float acc[2][8][4];
    #pragma unroll
    for (int i = 0; i < 2; ++i)
        #pragma unroll
        for (int j = 0; j < 8; ++j)
            #pragma unroll
            for (int t = 0; t < 4; ++t) acc[i][j][t] = 0.0f;

    float4 stg[8];  // staging: 4 chunks A, 4 chunks B

    // chunk mapping: cid = tid + i*256; row = cid>>3; kcol = (cid&7)*4
    #pragma unroll
    for (int i = 0; i < 4; ++i) {
        int cid = tid + i * 256;
        int mr = cid >> 3, kc = (cid & 7) * 4;
        stg[i]     = *(const float4*)(A  + (long)(m0 + mr) * K + kc);
        stg[4 + i] = *(const float4*)(Bm + (long)(n0 + mr) * K + kc);
    }

    const int T = K / GBK;
    for (int t = 0; t < T; ++t) {
        // store staged tile to smem with tf32 rounding
        #pragma unroll
        for (int i = 0; i < 4; ++i) {
            int cid = tid + i * 256;
            int mr = cid >> 3, kc = (cid & 7) * 4;
            float4 v = stg[i];
            *(float4*)(&As[mr * PAD + kc]) =
                make_float4(tf32r(v.x), tf32r(v.y), tf32r(v.z), tf32r(v.w));
            v = stg[4 + i];
            *(float4*)(&Bs[mr * PAD + kc]) =
                make_float4(tf32r(v.x), tf32r(v.y), tf32r(v.z), tf32r(v.w));
        }
        __syncthreads();

        // prefetch next tile
        if (t + 1 < T) {
            int k0 = (t + 1) * GBK;
            #pragma unroll
            for (int i = 0; i < 4; ++i) {
                int cid = tid + i * 256;
                int mr = cid >> 3, kc = (cid & 7) * 4;
                stg[i]     = *(const float4*)(A  + (long)(m0 + mr) * K + k0 + kc);
                stg[4 + i] = *(const float4*)(Bm + (long)(n0 + mr) * K + k0 + kc);
            }
        }

        // compute 4 k-steps of 8
        #pragma unroll
        for (int kk = 0; kk < 4; ++kk) {
            const int kb = kk * 8;
            float af[2][4], bf[8][2];
            #pragma unroll
            for (int i = 0; i < 2; ++i) {
                int r = wm * 32 + i * 16;
                af[i][0] = As[(r + ly)     * PAD + kb + lc];
                af[i][1] = As[(r + ly + 8) * PAD + kb + lc];
                af[i][2] = As[(r + ly)     * PAD + kb + lc + 4];
                af[i][3] = As[(r + ly + 8) * PAD + kb + lc + 4];
            }
            #pragma unroll
            for (int j = 0; j < 8; ++j) {
                int c = wn * 64 + j * 8;
                bf[j][0] = Bs[(c + ly) * PAD + kb + lc];
                bf[j][1] = Bs[(c + ly) * PAD + kb + lc + 4];
            }
            #pragma unroll
            for (int i = 0; i < 2; ++i)
                #pragma unroll
                for (int j = 0; j < 8; ++j) mma_tf32(acc[i][j], af[i], bf[j]);
        }
        __syncthreads();
    }

    // epilogue: bias + optional residual
    #pragma unroll
    for (int i = 0; i < 2; ++i) {
        int r = m0 + wm * 32 + i * 16 + ly;
        #pragma unroll
        for (int j = 0; j < 8; ++j) {
            int c = n0 + wn * 64 + j * 8 + lc * 2;
            float b0 = bias[c], b1 = bias[c + 1];
            float v0 = acc[i][j][0] + b0, v1 = acc[i][j][1] + b1;
            float v2 = acc[i][j][2] + b0, v3 = acc[i][j][3] + b1;
            long o0 = (long)r * N + c;
            long o1 = (long)(r + 8) * N + c;
            if (res) {
                float2 r0 = *(const float2*)(res + o0);
                float2 r1 = *(const float2*)(res + o1);
                v0 += r0.x; v1 += r0.y; v2 += r1.x; v3 += r1.y;
            }
            *(float2*)(out + o0) = make_float2(v0, v1);
            *(float2*)(out + o1) = make_float2(v2, v3);
        }
    }
}

// ---------------- Windowed attention, one block per (window, head) ------------------
__global__ __launch_bounds__(256)
void attn_kernel(const float* __restrict__ qkv, const float* __restrict__ rpb,
                 const float* __restrict__ x, float* __restrict__ x1) {
    const int head = blockIdx.x & 15;
    const int win  = blockIdx.x >> 4;
    const int b    = win >> 6;
    const int wi   = (win >> 3) & 7;
    const int wj   = win & 7;
    const int tid  = threadIdx.x;

    __shared__ float q[WS2_][HD_];
    __shared__ float k[WS2_][HD_];
    __shared__ float v[WS2_][HD_];
    __shared__ float s[WS2_][WS2_ + 1];

    for (int idx = tid; idx < WS2_ * HD_; idx += 256) {
        int p = idx >> 5, d = idx & 31;
        int token = (wi * 7 + p / 7) * 56 + (wj * 7 + p % 7);
        long base = ((long)b * N_ + token) * THREEC_ + head * HD_ + d;
        q[p][d] = qkv[base];
        k[p][d] = qkv[base + C_];
        v[p][d] = qkv[base + 2 * C_];
    }
    __syncthreads();

    const float scale = 0.17677669529663687f;
    for (int idx = tid; idx < WS2_ * WS2_; idx += 256) {
        int i = idx / WS2_, j = idx - i * WS2_;
        float acc = 0.0f;
        #pragma unroll
        for (int d = 0; d < HD_; ++d) acc = fmaf(q[i][d], k[j][d], acc);
        int dpi = (i / 7) - (j / 7) + 6;
        int dpj = (i % 7) - (j % 7) + 6;
        s[i][j] = acc * scale + rpb[(dpi * 13 + dpj) * NH_ + head];
    }
    __syncthreads();

    if (tid < WS2_) {
        float mx = -1e30f;
        #pragma unroll
        for (int j = 0; j < WS2_; ++j) mx = fmaxf(mx, s[tid][j]);
        float sum = 0.0f;
        #pragma unroll
        for (int j = 0; j < WS2_; ++j) { float e = __expf(s[tid][j] - mx); s[tid][j] = e; sum += e; }
        float inv = 1.0f / sum;
        #pragma unroll
        for (int j = 0; j < WS2_; ++j) s[tid][j] *= inv;
    }
    __syncthreads();

    for (int idx = tid; idx < WS2_ * HD_; idx += 256) {
        int i = idx >> 5, d = idx & 31;
        float acc = 0.0f;
        #pragma unroll
        for (int j = 0; j < WS2_; ++j) acc = fmaf(s[i][j], v[j][d], acc);
        int token = (wi * 7 + i / 7) * 56 + (wj * 7 + i % 7);
        long o = ((long)b * N_ + token) * C_ + head * HD_ + d;
        x1[o] = x[o] + acc;
    }
}

// ---------------- depthwise 3x3 (NHWC) + bias + exact GELU --------------------------
__global__ __launch_bounds__(256)
void dwconv_gelu_kernel(const float* __restrict__ h2, const float* __restrict__ w,
                        const float* __restrict__ bias, float* __restrict__ out) {
    __shared__ float ws[256 * 9];
    long idx = (long)blockIdx.x * 256 + threadIdx.x;
    int c = (int)(idx & (HID_ - 1));
    int c0 = (int)((blockIdx.x * 256L) & (HID_ - 1));
    #pragma unroll
    for (int t = 0; t < 9; ++t) ws[threadIdx.x * 9 + t] = w[(c0 + threadIdx.x) * 9 + t];
    __syncthreads();

    long sp = idx >> 11;
    int wcol = (int)(sp % 56);
    long t2 = sp / 56;
    int hrow = (int)(t2 % 56);
    int bb = (int)(t2 / 56);
    const float* wt = &ws[(c - c0) * 9];

    float acc = bias[c];
    #pragma unroll
    for (int dy = 0; dy < 3; ++dy) {
        int hh = hrow + dy - 1;
        if (hh < 0 || hh >= 56) continue;
        #pragma unroll
        for (int dx = 0; dx < 3; ++dx) {
            int ww = wcol + dx - 1;
            if (ww < 0 || ww >= 56) continue;
            acc = fmaf(h2[(((long)bb * 56 + hh) * 56 + ww) * HID_ + c], wt[dy * 3 + dx], acc);
        }
    }
    out[idx] = 0.5f * acc * (1.0f + erff(acc * 0.70710678118654752f));
}

// ---------------- launch ----------------
extern "C" void kernel_launch(void* const* d_in, const int* in_sizes, int n_in,
                              void* d_out, int out_size) {
    const float* x       = (const float*)d_in[0];
    const float* norm1_g = (const float*)d_in[3];
    const float* norm1_b = (const float*)d_in[4];
    const float* norm2_g = (const float*)d_in[5];
    const float* norm2_b = (const float*)d_in[6];
    const float* qkv_w   = (const float*)d_in[7];
    const float* qkv_b   = (const float*)d_in[8];
    const float* rpb     = (const float*)d_in[9];
    const float* fc1_w   = (const float*)d_in[10];
    const float* fc1_b   = (const float*)d_in[11];
    const float* dw_w    = (const float*)d_in[12];
    const float* dw_b    = (const float*)d_in[13];
    const float* fc2_w   = (const float*)d_in[14];
    const float* fc2_b   = (const float*)d_in[15];
    float* out = (float*)d_out;

    float *p_h, *p_qkv, *p_x1, *p_h2, *p_h3;
    cudaGetSymbolAddress((void**)&p_h,   g_h);
    cudaGetSymbolAddress((void**)&p_qkv, g_qkv);
    cudaGetSymbolAddress((void**)&p_x1,  g_x1);
    cudaGetSymbolAddress((void**)&p_h2,  g_h2);
    cudaGetSymbolAddress((void**)&p_h3,  g_h3);

    // 1) LN1
    ln_kernel<<<TOK_, 256>>>(x, norm1_g, norm1_b, p_h);
    // 2) QKV GEMM: [25088,512] x [1536,512]^T
    gemm_tf32_kernel<<<dim3(THREEC_ / GBN, TOK_ / GBM), 256>>>(
        p_h, qkv_w, qkv_b, nullptr, p_qkv, TOK_, THREEC_, C_);
    // 3) windowed attention + residual -> x1
    attn_kernel<<<B_ * 64 * NH_, 256>>>(p_qkv, rpb, x, p_x1);
    // 4) LN2
    ln_kernel<<<TOK_, 256>>>(p_x1, norm2_g, norm2_b, p_h);
    // 5) fc1 GEMM: [25088,512] x [2048,512]^T
    gemm_tf32_kernel<<<dim3(HID_ / GBN, TOK_ / GBM), 256>>>(
        p_h, fc1_w, fc1_b, nullptr, p_h2, TOK_, HID_, C_);
    // 6) depthwise conv + bias + GELU
    dwconv_gelu_kernel<<<(unsigned)(((long)TOK_ * HID_) / 256), 256>>>(p_h2, dw_w, dw_b, p_h3);
    // 7) fc2 GEMM + bias + residual(x1) -> out
    gemm_tf32_kernel<<<dim3(C_ / GBN, TOK_ / GBM), 256>>>(
        p_h3, fc2_w, fc2_b, p_x1, out, TOK_, C_, HID_);
}

// round 4
// speedup vs baseline: 3.1584x; 1.3644x over previous
#include <cuda_runtime.h>
#include <cuda_fp16.h>
#include <math.h>
#include <stdint.h>

// ---------------- problem constants ----------------
#define B_   8
#define HH_  56
#define WW_  56
#define N_   (HH_*WW_)          // 3136
#define C_   512
#define NH_  16
#define HD_  32
#define WS_  7
#define WS2_ 49
#define HID_ 2048
#define TOK_ (B_*N_)            // 25088
#define THREEC_ (3*C_)          // 1536

// ---------------- scratch ----------------
static __device__ __half g_hh  [(size_t)TOK_*C_];       // LN out (half)
static __device__ __half g_qkvh[(size_t)TOK_*THREEC_];  // qkv (half)
static __device__ float  g_x1  [(size_t)TOK_*C_];       // x + attn (fp32)
static __device__ __half g_h2h [(size_t)TOK_*HID_];     // fc1 out (half)
static __device__ __half g_h3h [(size_t)TOK_*HID_];     // gelu out (half)
static __device__ __half g_wq  [(size_t)THREEC_*C_];
static __device__ __half g_wf1 [(size_t)HID_*C_];
static __device__ __half g_wf2 [(size_t)C_*HID_];

// ---------------- fp32 -> fp16 conversion ----------------
__global__ __launch_bounds__(256)
void f2h_kernel(const float4* __restrict__ in, __half2* __restrict__ out, int n4) {
    int i = blockIdx.x * 256 + threadIdx.x;
    if (i >= n4) return;
    float4 v = in[i];
    out[2 * i]     = __floats2half2_rn(v.x, v.y);
    out[2 * i + 1] = __floats2half2_rn(v.z, v.w);
}

// ---------------- block reduce ----------------
__inline__ __device__ float blockReduceSum256(float val) {
    __shared__ float sh[8];
    __shared__ float resv;
    int lane = threadIdx.x & 31, wid = threadIdx.x >> 5;
    #pragma unroll
    for (int o = 16; o > 0; o >>= 1) val += __shfl_down_sync(0xffffffffu, val, o);
    if (lane == 0) sh[wid] = val;
    __syncthreads();
    if (wid == 0) {
        float v = (lane < 8) ? sh[lane] : 0.0f;
        #pragma unroll
        for (int o = 4; o > 0; o >>= 1) v += __shfl_down_sync(0xffffffffu, v, o);
        if (lane == 0) resv = v;
    }
    __syncthreads();
    return resv;
}

// ---------------- LayerNorm (fp32 in, half out) ----------------
__global__ __launch_bounds__(256)
void ln_kernel(const float* __restrict__ x, const float* __restrict__ g,
               const float* __restrict__ b, __half* __restrict__ out) {
    long row = blockIdx.x;
    const float* xr = x + row * C_;
    float v0 = xr[threadIdx.x];
    float v1 = xr[threadIdx.x + 256];
    float mu = blockReduceSum256(v0 + v1) * (1.0f / C_);
    float d0 = v0 - mu, d1 = v1 - mu;
    float var = blockReduceSum256(d0 * d0 + d1 * d1) * (1.0f / C_);
    float inv = rsqrtf(var + 1e-5f);
    __half* o = out + row * C_;
    o[threadIdx.x]       = __float2half_rn(d0 * inv * g[threadIdx.x]       + b[threadIdx.x]);
    o[threadIdx.x + 256] = __float2half_rn(d1 * inv * g[threadIdx.x + 256] + b[threadIdx.x + 256]);
}

// ---------------- FP16 tensor-core GEMM (mma.sync m16n8k16, fp32 accum) -------------
// out[M,N] = A[M,K] @ B[N,K]^T + bias[N] (+res). M%128==0, N%128==0, K%32==0.
#define BM 128
#define BN 128
#define BKH 32          // K halves per stage
#define LST 40          // smem row stride in halves (pad 8)

__device__ __forceinline__ void cpa16(uint32_t s, const void* g) {
    asm volatile("cp.async.ca.shared.global [%0], [%1], 16;" :: "r"(s), "l"(g));
}
__device__ __forceinline__ void mma_f16(float* c, const uint32_t* a, const uint32_t* b) {
    asm volatile(
        "mma.sync.aligned.m16n8k16.row.col.f32.f16.f16.f32 "
        "{%0,%1,%2,%3}, {%4,%5,%6,%7}, {%8,%9}, {%0,%1,%2,%3};"
        : "+f"(c[0]), "+f"(c[1]), "+f"(c[2]), "+f"(c[3])
        : "r"(a[0]), "r"(a[1]), "r"(a[2]), "r"(a[3]), "r"(b[0]), "r"(b[1]));
}

template<bool OUT_HALF, bool HAS_RES>
__global__ __launch_bounds__(256, 2)
void gemm_h_kernel(const __half* __restrict__ A, const __half* __restrict__ Bm,
                   const float* __restrict__ bias, const float* __restrict__ res,
                   void* __restrict__ outv, int M, int N, int K) {
    __shared__ __half As[2][BM * LST];
    __shared__ __half Bs[2][BN * LST];
    const int tid = threadIdx.x;
    const int lane = tid & 31, wid = tid >> 5;
    const int wm = wid & 3, wn = wid >> 2;       // warp tile 32(M) x 64(N)
    const int g8 = lane >> 2, tig = lane & 3;
    const int m0 = blockIdx.y * BM, n0 = blockIdx.x * BN;

    const uint32_t sAs0 = (uint32_t)__cvta_generic_to_shared(&As[0][0]);
    const uint32_t sBs0 = (uint32_t)__cvta_generic_to_shared(&Bs[0][0]);

    float acc[2][8][4];
    #pragma unroll
    for (int i = 0; i < 2; ++i)
        #pragma unroll
        for (int j = 0; j < 8; ++j)
            #pragma unroll
            for (int t = 0; t < 4; ++t) acc[i][j][t] = 0.0f;

    const int T = K / BKH;

    // stage loader: 128 rows x 32 halves per matrix; 2 x 16B chunks/thread/matrix
    auto load_stage = [&](int t, int s) {
        const int k0 = t * BKH;
        #pragma unroll
        for (int i = 0; i < 2; ++i) {
            int cid = tid + i * 256;
            int row = cid >> 2, q = cid & 3;
            uint32_t so = (uint32_t)(s * BM * LST + row * LST + q * 8) * 2u;
            cpa16(sAs0 + so, A + (long)(m0 + row) * K + k0 + q * 8);
            cpa16(sBs0 + so, Bm + (long)(n0 + row) * K + k0 + q * 8);
        }
    };

    load_stage(0, 0);
    asm volatile("cp.async.commit_group;");

    for (int t = 0; t < T; ++t) {
        const int s = t & 1;
        if (t + 1 < T) {
            load_stage(t + 1, s ^ 1);
            asm volatile("cp.async.commit_group;");
            asm volatile("cp.async.wait_group 1;");
        } else {
            asm volatile("cp.async.wait_group 0;");
        }
        __syncthreads();

        #pragma unroll
        for (int kk = 0; kk < 2; ++kk) {
            const int kb = kk * 16;
            uint32_t a[2][4], b[8][2];
            #pragma unroll
            for (int i = 0; i < 2; ++i) {
                int r = wm * 32 + i * 16 + g8;
                a[i][0] = *(const uint32_t*)&As[s][r * LST + kb + tig * 2];
                a[i][1] = *(const uint32_t*)&As[s][(r + 8) * LST + kb + tig * 2];
                a[i][2] = *(const uint32_t*)&As[s][r * LST + kb + tig * 2 + 8];
                a[i][3] = *(const uint32_t*)&As[s][(r + 8) * LST + kb + tig * 2 + 8];
            }
            #pragma unroll
            for (int j = 0; j < 8; ++j) {
                int cn = wn * 64 + j * 8 + g8;
                b[j][0] = *(const uint32_t*)&Bs[s][cn * LST + kb + tig * 2];
                b[j][1] = *(const uint32_t*)&Bs[s][cn * LST + kb + tig * 2 + 8];
            }
            #pragma unroll
            for (int i = 0; i < 2; ++i)
                #pragma unroll
                for (int j = 0; j < 8; ++j) mma_f16(acc[i][j], a[i], b[j]);
        }
        __syncthreads();
    }

    // epilogue
    #pragma unroll
    for (int i = 0; i < 2; ++i) {
        int r = m0 + wm * 32 + i * 16 + g8;
        #pragma unroll
        for (int j = 0; j < 8; ++j) {
            int n = n0 + wn * 64 + j * 8 + tig * 2;
            float b0 = bias[n], b1 = bias[n + 1];
            float v0 = acc[i][j][0] + b0, v1 = acc[i][j][1] + b1;
            float v2 = acc[i][j][2] + b0, v3 = acc[i][j][3] + b1;
            long o0 = (long)r * N + n;
            long o1 = (long)(r + 8) * N + n;
            if (HAS_RES) {
                float2 r0 = *(const float2*)(res + o0);
                float2 r1 = *(const float2*)(res + o1);
                v0 += r0.x; v1 += r0.y; v2 += r1.x; v3 += r1.y;
            }
            if (OUT_HALF) {
                __half* out = (__half*)outv;
                *(__half2*)(out + o0) = __floats2half2_rn(v0, v1);
                *(__half2*)(out + o1) = __floats2half2_rn(v2, v3);
            } else {
                float* out = (float*)outv;
                *(float2*)(out + o0) = make_float2(v0, v1);
                *(float2*)(out + o1) = make_float2(v2, v3);
            }
        }
    }
}

// ---------------- Windowed attention (half qkv in, fp32 x1 out) ---------------------
__global__ __launch_bounds__(256)
void attn_kernel(const __half* __restrict__ qkv, const float* __restrict__ rpb,
                 const float* __restrict__ x, float* __restrict__ x1) {
    const int head = blockIdx.x & 15;
    const int win  = blockIdx.x >> 4;
    const int b    = win >> 6;
    const int wi   = (win >> 3) & 7;
    const int wj   = win & 7;
    const int tid  = threadIdx.x;

    __shared__ float q[WS2_][HD_];
    __shared__ float k[WS2_][HD_];
    __shared__ float v[WS2_][HD_];
    __shared__ float s[WS2_][WS2_ + 1];

    for (int idx = tid; idx < WS2_ * HD_; idx += 256) {
        int p = idx >> 5, d = idx & 31;
        int token = (wi * 7 + p / 7) * 56 + (wj * 7 + p % 7);
        long base = ((long)b * N_ + token) * THREEC_ + head * HD_ + d;
        q[p][d] = __half2float(qkv[base]);
        k[p][d] = __half2float(qkv[base + C_]);
        v[p][d] = __half2float(qkv[base + 2 * C_]);
    }
    __syncthreads();

    const float scale = 0.17677669529663687f;
    for (int idx = tid; idx < WS2_ * WS2_; idx += 256) {
        int i = idx / WS2_, j = idx - i * WS2_;
        float acc = 0.0f;
        #pragma unroll
        for (int d = 0; d < HD_; ++d) acc = fmaf(q[i][d], k[j][d], acc);
        int dpi = (i / 7) - (j / 7) + 6;
        int dpj = (i % 7) - (j % 7) + 6;
        s[i][j] = acc * scale + rpb[(dpi * 13 + dpj) * NH_ + head];
    }
    __syncthreads();

    if (tid < WS2_) {
        float mx = -1e30f;
        #pragma unroll
        for (int j = 0; j < WS2_; ++j) mx = fmaxf(mx, s[tid][j]);
        float sum = 0.0f;
        #pragma unroll
        for (int j = 0; j < WS2_; ++j) { float e = __expf(s[tid][j] - mx); s[tid][j] = e; sum += e; }
        float inv = 1.0f / sum;
        #pragma unroll
        for (int j = 0; j < WS2_; ++j) s[tid][j] *= inv;
    }
    __syncthreads();

    for (int idx = tid; idx < WS2_ * HD_; idx += 256) {
        int i = idx >> 5, d = idx & 31;
        float acc = 0.0f;
        #pragma unroll
        for (int j = 0; j < WS2_; ++j) acc = fmaf(s[i][j], v[j][d], acc);
        int token = (wi * 7 + i / 7) * 56 + (wj * 7 + i % 7);
        long o = ((long)b * N_ + token) * C_ + head * HD_ + d;
        x1[o] = x[o] + acc;
    }
}

// ---------------- depthwise 3x3 + bias + exact GELU (half in/out, 2 ch/thread) ------
__global__ __launch_bounds__(256)
void dwconv_gelu_kernel(const __half2* __restrict__ h2, const float* __restrict__ w,
                        const float* __restrict__ bias, __half2* __restrict__ out) {
    __shared__ float ws[512 * 9];
    long idx = (long)blockIdx.x * 256 + threadIdx.x;     // channel-pair index
    int cp  = (int)(idx & 1023);                          // pair within 1024
    int cp0 = (int)((blockIdx.x * 256L) & 1023);          // block-start pair
    // load weights for 512 channels covered by this block (contiguous in w)
    for (int q = threadIdx.x; q < 512 * 9; q += 256) ws[q] = w[(long)(2 * cp0) * 9 + q];
    __syncthreads();

    long sp = idx >> 10;
    int wcol = (int)(sp % 56);
    long t2 = sp / 56;
    int hrow = (int)(t2 % 56);
    int bb = (int)(t2 / 56);
    int lc = cp - cp0;                                    // 0..255
    const float* w0 = &ws[(2 * lc) * 9];
    const float* w1 = w0 + 9;

    int c = cp * 2;
    float a0 = bias[c], a1 = bias[c + 1];
    #pragma unroll
    for (int dy = 0; dy < 3; ++dy) {
        int hh = hrow + dy - 1;
        if (hh < 0 || hh >= 56) continue;
        long rowbase = (((long)bb * 56 + hh) * 56) * 1024 + cp;
        #pragma unroll
        for (int dx = 0; dx < 3; ++dx) {
            int ww = wcol + dx - 1;
            if (ww < 0 || ww >= 56) continue;
            float2 v = __half22float2(h2[rowbase + (long)ww * 1024]);
            a0 = fmaf(v.x, w0[dy * 3 + dx], a0);
            a1 = fmaf(v.y, w1[dy * 3 + dx], a1);
        }
    }
    float g0 = 0.5f * a0 * (1.0f + erff(a0 * 0.70710678118654752f));
    float g1 = 0.5f * a1 * (1.0f + erff(a1 * 0.70710678118654752f));
    out[idx] = __floats2half2_rn(g0, g1);
}

// ---------------- launch ----------------
extern "C" void kernel_launch(void* const* d_in, const int* in_sizes, int n_in,
                              void* d_out, int out_size) {
    const float* x       = (const float*)d_in[0];
    const float* norm1_g = (const float*)d_in[3];
    const float* norm1_b = (const float*)d_in[4];
    const float* norm2_g = (const float*)d_in[5];
    const float* norm2_b = (const float*)d_in[6];
    const float* qkv_w   = (const float*)d_in[7];
    const float* qkv_b   = (const float*)d_in[8];
    const float* rpb     = (const float*)d_in[9];
    const float* fc1_w   = (const float*)d_in[10];
    const float* fc1_b   = (const float*)d_in[11];
    const float* dw_w    = (const float*)d_in[12];
    const float* dw_b    = (const float*)d_in[13];
    const float* fc2_w   = (const float*)d_in[14];
    const float* fc2_b   = (const float*)d_in[15];
    float* out = (float*)d_out;

    __half *p_hh, *p_qkvh, *p_h2h, *p_h3h, *p_wq, *p_wf1, *p_wf2;
    float *p_x1;
    cudaGetSymbolAddress((void**)&p_hh,   g_hh);
    cudaGetSymbolAddress((void**)&p_qkvh, g_qkvh);
    cudaGetSymbolAddress((void**)&p_x1,   g_x1);
    cudaGetSymbolAddress((void**)&p_h2h,  g_h2h);
    cudaGetSymbolAddress((void**)&p_h3h,  g_h3h);
    cudaGetSymbolAddress((void**)&p_wq,   g_wq);
    cudaGetSymbolAddress((void**)&p_wf1,  g_wf1);
    cudaGetSymbolAddress((void**)&p_wf2,  g_wf2);

    // 0) weight conversions (fp32 -> fp16)
    f2h_kernel<<<(THREEC_ * C_ / 4 + 255) / 256, 256>>>((const float4*)qkv_w, (__half2*)p_wq, THREEC_ * C_ / 4);
    f2h_kernel<<<(HID_ * C_ / 4 + 255) / 256, 256>>>((const float4*)fc1_w, (__half2*)p_wf1, HID_ * C_ / 4);
    f2h_kernel<<<(C_ * HID_ / 4 + 255) / 256, 256>>>((const float4*)fc2_w, (__half2*)p_wf2, C_ * HID_ / 4);

    // 1) LN1
    ln_kernel<<<TOK_, 256>>>(x, norm1_g, norm1_b, p_hh);
    // 2) QKV GEMM
    gemm_h_kernel<true, false><<<dim3(THREEC_ / BN, TOK_ / BM), 256>>>(
        p_hh, p_wq, qkv_b, nullptr, p_qkvh, TOK_, THREEC_, C_);
    // 3) windowed attention + residual
    attn_kernel<<<B_ * 64 * NH_, 256>>>(p_qkvh, rpb, x, p_x1);
    // 4) LN2
    ln_kernel<<<TOK_, 256>>>(p_x1, norm2_g, norm2_b, p_hh);
    // 5) fc1 GEMM
    gemm_h_kernel<true, false><<<dim3(HID_ / BN, TOK_ / BM), 256>>>(
        p_hh, p_wf1, fc1_b, nullptr, p_h2h, TOK_, HID_, C_);
    // 6) depthwise conv + GELU
    dwconv_gelu_kernel<<<(unsigned)(((long)TOK_ * HID_ / 2) / 256), 256>>>(
        (const __half2*)p_h2h, dw_w, dw_b, (__half2*)p_h3h);
    // 7) fc2 GEMM + residual -> out
    gemm_h_kernel<false, true><<<dim3(C_ / BN, TOK_ / BM), 256>>>(
        p_h3h, p_wf2, fc2_b, p_x1, out, TOK_, C_, HID_);
}

// round 5
// speedup vs baseline: 4.3366x; 1.3730x over previous
#include <cuda_runtime.h>
#include <cuda_fp16.h>
#include <math.h>
#include <stdint.h>

// ---------------- problem constants ----------------
#define B_   8
#define HH_  56
#define WW_  56
#define N_   (HH_*WW_)          // 3136
#define C_   512
#define NH_  16
#define HD_  32
#define WS_  7
#define WS2_ 49
#define HID_ 2048
#define TOK_ (B_*N_)            // 25088
#define THREEC_ (3*C_)          // 1536

// ---------------- scratch ----------------
static __device__ __half g_hh  [(size_t)TOK_*C_];
static __device__ __half g_qkvh[(size_t)TOK_*THREEC_];
static __device__ float  g_x1  [(size_t)TOK_*C_];
static __device__ __half g_h2h [(size_t)TOK_*HID_];
static __device__ __half g_h3h [(size_t)TOK_*HID_];
static __device__ __half g_wq  [(size_t)THREEC_*C_];
static __device__ __half g_wf1 [(size_t)HID_*C_];
static __device__ __half g_wf2 [(size_t)C_*HID_];

// ---------------- fp32 -> fp16 conversion ----------------
__global__ __launch_bounds__(256)
void f2h_kernel(const float4* __restrict__ in, __half2* __restrict__ out, int n4) {
    int i = blockIdx.x * 256 + threadIdx.x;
    if (i >= n4) return;
    float4 v = in[i];
    out[2 * i]     = __floats2half2_rn(v.x, v.y);
    out[2 * i + 1] = __floats2half2_rn(v.z, v.w);
}

// ---------------- LayerNorm: warp per row, float4, no block barriers in reduce ------
__global__ __launch_bounds__(256)
void ln_kernel(const float* __restrict__ x, const float* __restrict__ g,
               const float* __restrict__ b, __half* __restrict__ out) {
    __shared__ float sg[C_], sb[C_];
    const int tid = threadIdx.x;
    sg[tid] = g[tid]; sg[tid + 256] = g[tid + 256];
    sb[tid] = b[tid]; sb[tid + 256] = b[tid + 256];
    __syncthreads();

    const int lane = tid & 31, wid = tid >> 5;
    const long row = (long)blockIdx.x * 8 + wid;
    const float4* xr = (const float4*)(x + row * C_);

    float4 v[4];
    float sum = 0.0f;
    #pragma unroll
    for (int k = 0; k < 4; ++k) {
        v[k] = xr[lane + k * 32];
        sum += v[k].x + v[k].y + v[k].z + v[k].w;
    }
    #pragma unroll
    for (int o = 16; o > 0; o >>= 1) sum += __shfl_xor_sync(0xffffffffu, sum, o);
    float mu = sum * (1.0f / C_);

    float vs = 0.0f;
    #pragma unroll
    for (int k = 0; k < 4; ++k) {
        float dx = v[k].x - mu, dy = v[k].y - mu, dz = v[k].z - mu, dw = v[k].w - mu;
        vs += dx * dx + dy * dy + dz * dz + dw * dw;
    }
    #pragma unroll
    for (int o = 16; o > 0; o >>= 1) vs += __shfl_xor_sync(0xffffffffu, vs, o);
    float inv = rsqrtf(vs * (1.0f / C_) + 1e-5f);

    __half2* orow = (__half2*)(out + row * C_);
    #pragma unroll
    for (int k = 0; k < 4; ++k) {
        int i4 = lane + k * 32, c = i4 * 4;
        float e0 = (v[k].x - mu) * inv * sg[c]     + sb[c];
        float e1 = (v[k].y - mu) * inv * sg[c + 1] + sb[c + 1];
        float e2 = (v[k].z - mu) * inv * sg[c + 2] + sb[c + 2];
        float e3 = (v[k].w - mu) * inv * sg[c + 3] + sb[c + 3];
        orow[i4 * 2]     = __floats2half2_rn(e0, e1);
        orow[i4 * 2 + 1] = __floats2half2_rn(e2, e3);
    }
}

// ---------------- FP16 tensor-core GEMM (ldmatrix + 3-stage cp.async) ---------------
// out[M,N] = A[M,K] @ B[N,K]^T + bias[N] (+res). M%128==0, N%128==0, K%32==0.
#define BM 128
#define BN 128
#define BKH 32
#define LST 40
#define STAGEH ((BM + BN) * LST)        // halves per stage
#define GSMEM (3 * STAGEH * 2)          // bytes

__device__ __forceinline__ void cpa16(uint32_t s, const void* g) {
    asm volatile("cp.async.ca.shared.global [%0], [%1], 16;" :: "r"(s), "l"(g));
}
__device__ __forceinline__ void ldsm4(uint32_t* r, uint32_t addr) {
    asm volatile("ldmatrix.sync.aligned.m8n8.x4.shared.b16 {%0,%1,%2,%3}, [%4];"
                 : "=r"(r[0]), "=r"(r[1]), "=r"(r[2]), "=r"(r[3]) : "r"(addr));
}
__device__ __forceinline__ void mma_f16(float* c, const uint32_t* a, const uint32_t* b) {
    asm volatile(
        "mma.sync.aligned.m16n8k16.row.col.f32.f16.f16.f32 "
        "{%0,%1,%2,%3}, {%4,%5,%6,%7}, {%8,%9}, {%0,%1,%2,%3};"
        : "+f"(c[0]), "+f"(c[1]), "+f"(c[2]), "+f"(c[3])
        : "r"(a[0]), "r"(a[1]), "r"(a[2]), "r"(a[3]), "r"(b[0]), "r"(b[1]));
}

template<bool OUT_HALF, bool HAS_RES>
__global__ __launch_bounds__(256, 2)
void gemm_h_kernel(const __half* __restrict__ A, const __half* __restrict__ Bm,
                   const float* __restrict__ bias, const float* __restrict__ res,
                   void* __restrict__ outv, int M, int N, int K) {
    extern __shared__ __half sm[];
    const uint32_t smb = (uint32_t)__cvta_generic_to_shared(sm);
    const int tid = threadIdx.x;
    const int lane = tid & 31, wid = tid >> 5;
    const int wm = wid & 3, wn = wid >> 2;         // warp tile 32(M) x 64(N)
    const int g8 = lane >> 2, tig = lane & 3;
    const int m0 = blockIdx.y * BM, n0 = blockIdx.x * BN;

    float acc[2][8][4];
    #pragma unroll
    for (int i = 0; i < 2; ++i)
        #pragma unroll
        for (int j = 0; j < 8; ++j)
            #pragma unroll
            for (int t = 0; t < 4; ++t) acc[i][j][t] = 0.0f;

    const int T = K / BKH;
    const int lrow = tid >> 2, lq = tid & 3;

    auto load_stage = [&](int t, int s) {
        const int k0 = t * BKH;
        uint32_t sa = smb + (uint32_t)(s * STAGEH + lrow * LST + lq * 8) * 2u;
        cpa16(sa, A + (long)(m0 + lrow) * K + k0 + lq * 8);
        cpa16(sa + BM * LST * 2u, Bm + (long)(n0 + lrow) * K + k0 + lq * 8);
        int row2 = lrow + 64;
        uint32_t sa2 = smb + (uint32_t)(s * STAGEH + row2 * LST + lq * 8) * 2u;
        cpa16(sa2, A + (long)(m0 + row2) * K + k0 + lq * 8);
        cpa16(sa2 + BM * LST * 2u, Bm + (long)(n0 + row2) * K + k0 + lq * 8);
    };

    load_stage(0, 0);
    asm volatile("cp.async.commit_group;");
    if (T > 1) { load_stage(1, 1); asm volatile("cp.async.commit_group;"); }

    // precomputed ldmatrix lane addressing
    const int a_r = (lane & 15), a_k = (lane >> 4) * 8;
    const int b_r = (lane & 7), b_t = (lane >> 4), b_k = ((lane >> 3) & 1) * 8;

    for (int t = 0; t < T; ++t) {
        const int s = t % 3;
        if (t + 2 < T) {
            load_stage(t + 2, (t + 2) % 3);
            asm volatile("cp.async.commit_group;");
            asm volatile("cp.async.wait_group 2;");
        } else if (t + 1 < T) {
            asm volatile("cp.async.wait_group 1;");
        } else {
            asm volatile("cp.async.wait_group 0;");
        }
        __syncthreads();

        const uint32_t sA = smb + (uint32_t)(s * STAGEH) * 2u;
        const uint32_t sB = sA + BM * LST * 2u;

        #pragma unroll
        for (int kk = 0; kk < 2; ++kk) {
            const int kb = kk * 16;
            uint32_t a[2][4], b[8][2];
            #pragma unroll
            for (int i = 0; i < 2; ++i)
                ldsm4(a[i], sA + (uint32_t)((wm * 32 + i * 16 + a_r) * LST + kb + a_k) * 2u);
            #pragma unroll
            for (int jp = 0; jp < 4; ++jp) {
                uint32_t r[4];
                ldsm4(r, sB + (uint32_t)((wn * 64 + (jp * 2 + b_t) * 8 + b_r) * LST + kb + b_k) * 2u);
                b[jp * 2][0] = r[0]; b[jp * 2][1] = r[1];
                b[jp * 2 + 1][0] = r[2]; b[jp * 2 + 1][1] = r[3];
            }
            #pragma unroll
            for (int i = 0; i < 2; ++i)
                #pragma unroll
                for (int j = 0; j < 8; ++j) mma_f16(acc[i][j], a[i], b[j]);
        }
        __syncthreads();
    }

    // epilogue
    #pragma unroll
    for (int i = 0; i < 2; ++i) {
        int r = m0 + wm * 32 + i * 16 + g8;
        #pragma unroll
        for (int j = 0; j < 8; ++j) {
            int n = n0 + wn * 64 + j * 8 + tig * 2;
            float b0 = bias[n], b1 = bias[n + 1];
            float v0 = acc[i][j][0] + b0, v1 = acc[i][j][1] + b1;
            float v2 = acc[i][j][2] + b0, v3 = acc[i][j][3] + b1;
            long o0 = (long)r * N + n;
            long o1 = (long)(r + 8) * N + n;
            if (HAS_RES) {
                float2 r0 = *(const float2*)(res + o0);
                float2 r1 = *(const float2*)(res + o1);
                v0 += r0.x; v1 += r0.y; v2 += r1.x; v3 += r1.y;
            }
            if (OUT_HALF) {
                __half* out = (__half*)outv;
                *(__half2*)(out + o0) = __floats2half2_rn(v0, v1);
                *(__half2*)(out + o1) = __floats2half2_rn(v2, v3);
            } else {
                float* out = (float*)outv;
                *(float2*)(out + o0) = make_float2(v0, v1);
                *(float2*)(out + o1) = make_float2(v2, v3);
            }
        }
    }
}

// ---------------- Windowed attention (padded smem: conflict-free) -------------------
__global__ __launch_bounds__(256)
void attn_kernel(const __half* __restrict__ qkv, const float* __restrict__ rpb,
                 const float* __restrict__ x, float* __restrict__ x1) {
    const int head = blockIdx.x & 15;
    const int win  = blockIdx.x >> 4;
    const int b    = win >> 6;
    const int wi   = (win >> 3) & 7;
    const int wj   = win & 7;
    const int tid  = threadIdx.x;

    __shared__ float q[WS2_][HD_ + 1];
    __shared__ float k[WS2_][HD_ + 1];
    __shared__ float v[WS2_][HD_ + 1];
    __shared__ float s[WS2_][WS2_ + 1];

    for (int idx = tid; idx < WS2_ * 16; idx += 256) {
        int p = idx >> 4, d2 = idx & 15;
        int token = (wi * 7 + p / 7) * 56 + (wj * 7 + p % 7);
        long base = ((long)b * N_ + token) * THREEC_ + head * HD_ + 2 * d2;
        float2 fq = __half22float2(*(const __half2*)(qkv + base));
        float2 fk = __half22float2(*(const __half2*)(qkv + base + C_));
        float2 fv = __half22float2(*(const __half2*)(qkv + base + 2 * C_));
        q[p][2 * d2] = fq.x; q[p][2 * d2 + 1] = fq.y;
        k[p][2 * d2] = fk.x; k[p][2 * d2 + 1] = fk.y;
        v[p][2 * d2] = fv.x; v[p][2 * d2 + 1] = fv.y;
    }
    __syncthreads();

    const float scale = 0.17677669529663687f;
    for (int idx = tid; idx < WS2_ * WS2_; idx += 256) {
        int i = idx / WS2_, j = idx - i * WS2_;
        float acc = 0.0f;
        #pragma unroll
        for (int d = 0; d < HD_; ++d) acc = fmaf(q[i][d], k[j][d], acc);
        int dpi = (i / 7) - (j / 7) + 6;
        int dpj = (i % 7) - (j % 7) + 6;
        s[i][j] = acc * scale + rpb[(dpi * 13 + dpj) * NH_ + head];
    }
    __syncthreads();

    if (tid < WS2_) {
        float mx = -1e30f;
        #pragma unroll
        for (int j = 0; j < WS2_; ++j) mx = fmaxf(mx, s[tid][j]);
        float sum = 0.0f;
        #pragma unroll
        for (int j = 0; j < WS2_; ++j) { float e = __expf(s[tid][j] - mx); s[tid][j] = e; sum += e; }
        float inv = 1.0f / sum;
        #pragma unroll
        for (int j = 0; j < WS2_; ++j) s[tid][j] *= inv;
    }
    __syncthreads();

    for (int idx = tid; idx < WS2_ * HD_; idx += 256) {
        int i = idx >> 5, d = idx & 31;
        float acc = 0.0f;
        #pragma unroll
        for (int j = 0; j < WS2_; ++j) acc = fmaf(s[i][j], v[j][d], acc);
        int token = (wi * 7 + i / 7) * 56 + (wj * 7 + i % 7);
        long o = ((long)b * N_ + token) * C_ + head * HD_ + d;
        x1[o] = x[o] + acc;
    }
}

// ---------------- depthwise 3x3 + bias + exact GELU (half2, 2 ch/thread) ------------
__global__ __launch_bounds__(256)
void dwconv_gelu_kernel(const __half2* __restrict__ h2, const float* __restrict__ w,
                        const float* __restrict__ bias, __half2* __restrict__ out) {
    __shared__ float ws[512 * 9];
    long idx = (long)blockIdx.x * 256 + threadIdx.x;
    int cp  = (int)(idx & 1023);
    int cp0 = (int)((blockIdx.x * 256L) & 1023);
    for (int q = threadIdx.x; q < 512 * 9; q += 256) ws[q] = w[(long)(2 * cp0) * 9 + q];
    __syncthreads();

    long sp = idx >> 10;
    int wcol = (int)(sp % 56);
    long t2 = sp / 56;
    int hrow = (int)(t2 % 56);
    int bb = (int)(t2 / 56);
    int lc = cp - cp0;
    const float* w0 = &ws[(2 * lc) * 9];
    const float* w1 = w0 + 9;

    int c = cp * 2;
    float a0 = bias[c], a1 = bias[c + 1];
    #pragma unroll
    for (int dy = 0; dy < 3; ++dy) {
        int hh = hrow + dy - 1;
        if (hh < 0 || hh >= 56) continue;
        long rowbase = (((long)bb * 56 + hh) * 56) * 1024 + cp;
        #pragma unroll
        for (int dx = 0; dx < 3; ++dx) {
            int ww = wcol + dx - 1;
            if (ww < 0 || ww >= 56) continue;
            float2 v = __half22float2(h2[rowbase + (long)ww * 1024]);
            a0 = fmaf(v.x, w0[dy * 3 + dx], a0);
            a1 = fmaf(v.y, w1[dy * 3 + dx], a1);
        }
    }
    float g0 = 0.5f * a0 * (1.0f + erff(a0 * 0.70710678118654752f));
    float g1 = 0.5f * a1 * (1.0f + erff(a1 * 0.70710678118654752f));
    out[idx] = __floats2half2_rn(g0, g1);
}

// ---------------- launch ----------------
extern "C" void kernel_launch(void* const* d_in, const int* in_sizes, int n_in,
                              void* d_out, int out_size) {
    const float* x       = (const float*)d_in[0];
    const float* norm1_g = (const float*)d_in[3];
    const float* norm1_b = (const float*)d_in[4];
    const float* norm2_g = (const float*)d_in[5];
    const float* norm2_b = (const float*)d_in[6];
    const float* qkv_w   = (const float*)d_in[7];
    const float* qkv_b   = (const float*)d_in[8];
    const float* rpb     = (const float*)d_in[9];
    const float* fc1_w   = (const float*)d_in[10];
    const float* fc1_b   = (const float*)d_in[11];
    const float* dw_w    = (const float*)d_in[12];
    const float* dw_b    = (const float*)d_in[13];
    const float* fc2_w   = (const float*)d_in[14];
    const float* fc2_b   = (const float*)d_in[15];
    float* out = (float*)d_out;

    __half *p_hh, *p_qkvh, *p_h2h, *p_h3h, *p_wq, *p_wf1, *p_wf2;
    float *p_x1;
    cudaGetSymbolAddress((void**)&p_hh,   g_hh);
    cudaGetSymbolAddress((void**)&p_qkvh, g_qkvh);
    cudaGetSymbolAddress((void**)&p_x1,   g_x1);
    cudaGetSymbolAddress((void**)&p_h2h,  g_h2h);
    cudaGetSymbolAddress((void**)&p_h3h,  g_h3h);
    cudaGetSymbolAddress((void**)&p_wq,   g_wq);
    cudaGetSymbolAddress((void**)&p_wf1,  g_wf1);
    cudaGetSymbolAddress((void**)&p_wf2,  g_wf2);

    cudaFuncSetAttribute(gemm_h_kernel<true, false>,
                         cudaFuncAttributeMaxDynamicSharedMemorySize, GSMEM);
    cudaFuncSetAttribute(gemm_h_kernel<false, true>,
                         cudaFuncAttributeMaxDynamicSharedMemorySize, GSMEM);

    // 0) weight conversions
    f2h_kernel<<<(THREEC_ * C_ / 4 + 255) / 256, 256>>>((const float4*)qkv_w, (__half2*)p_wq, THREEC_ * C_ / 4);
    f2h_kernel<<<(HID_ * C_ / 4 + 255) / 256, 256>>>((const float4*)fc1_w, (__half2*)p_wf1, HID_ * C_ / 4);
    f2h_kernel<<<(C_ * HID_ / 4 + 255) / 256, 256>>>((const float4*)fc2_w, (__half2*)p_wf2, C_ * HID_ / 4);

    // 1) LN1
    ln_kernel<<<TOK_ / 8, 256>>>(x, norm1_g, norm1_b, p_hh);
    // 2) QKV GEMM
    gemm_h_kernel<true, false><<<dim3(THREEC_ / BN, TOK_ / BM), 256, GSMEM>>>(
        p_hh, p_wq, qkv_b, nullptr, p_qkvh, TOK_, THREEC_, C_);
    // 3) windowed attention + residual
    attn_kernel<<<B_ * 64 * NH_, 256>>>(p_qkvh, rpb, x, p_x1);
    // 4) LN2
    ln_kernel<<<TOK_ / 8, 256>>>(p_x1, norm2_g, norm2_b, p_hh);
    // 5) fc1 GEMM
    gemm_h_kernel<true, false><<<dim3(HID_ / BN, TOK_ / BM), 256, GSMEM>>>(
        p_hh, p_wf1, fc1_b, nullptr, p_h2h, TOK_, HID_, C_);
    // 6) depthwise conv + GELU
    dwconv_gelu_kernel<<<(unsigned)(((long)TOK_ * HID_ / 2) / 256), 256>>>(
        (const __half2*)p_h2h, dw_w, dw_b, (__half2*)p_h3h);
    // 7) fc2 GEMM + residual -> out
    gemm_h_kernel<false, true><<<dim3(C_ / BN, TOK_ / BM), 256, GSMEM>>>(
        p_h3h, p_wf2, fc2_b, p_x1, out, TOK_, C_, HID_);
}

// round 6
// speedup vs baseline: 5.8186x; 1.3418x over previous
#include <cuda_runtime.h>
#include <cuda_fp16.h>
#include <math.h>
#include <stdint.h>

// ---------------- problem constants ----------------
#define B_   8
#define HH_  56
#define WW_  56
#define N_   (HH_*WW_)          // 3136
#define C_   512
#define NH_  16
#define HD_  32
#define WS_  7
#define WS2_ 49
#define HID_ 2048
#define TOK_ (B_*N_)            // 25088
#define THREEC_ (3*C_)          // 1536

// ---------------- scratch ----------------
static __device__ __half g_hh  [(size_t)TOK_*C_];
static __device__ __half g_qkvh[(size_t)TOK_*THREEC_];
static __device__ float  g_x1  [(size_t)TOK_*C_];
static __device__ __half g_h2h [(size_t)TOK_*HID_];
static __device__ __half g_h3h [(size_t)TOK_*HID_];
static __device__ __half g_wq  [(size_t)THREEC_*C_];
static __device__ __half g_wf1 [(size_t)HID_*C_];
static __device__ __half g_wf2 [(size_t)C_*HID_];

// ---------------- fp32 -> fp16 conversion ----------------
__global__ __launch_bounds__(256)
void f2h_kernel(const float4* __restrict__ in, __half2* __restrict__ out, int n4) {
    int i = blockIdx.x * 256 + threadIdx.x;
    if (i >= n4) return;
    float4 v = in[i];
    out[2 * i]     = __floats2half2_rn(v.x, v.y);
    out[2 * i + 1] = __floats2half2_rn(v.z, v.w);
}

// ---------------- LayerNorm: warp per row ----------------
__global__ __launch_bounds__(256)
void ln_kernel(const float* __restrict__ x, const float* __restrict__ g,
               const float* __restrict__ b, __half* __restrict__ out) {
    __shared__ float sg[C_], sb[C_];
    const int tid = threadIdx.x;
    sg[tid] = g[tid]; sg[tid + 256] = g[tid + 256];
    sb[tid] = b[tid]; sb[tid + 256] = b[tid + 256];
    __syncthreads();

    const int lane = tid & 31, wid = tid >> 5;
    const long row = (long)blockIdx.x * 8 + wid;
    const float4* xr = (const float4*)(x + row * C_);

    float4 v[4];
    float sum = 0.0f;
    #pragma unroll
    for (int k = 0; k < 4; ++k) {
        v[k] = xr[lane + k * 32];
        sum += v[k].x + v[k].y + v[k].z + v[k].w;
    }
    #pragma unroll
    for (int o = 16; o > 0; o >>= 1) sum += __shfl_xor_sync(0xffffffffu, sum, o);
    float mu = sum * (1.0f / C_);

    float vs = 0.0f;
    #pragma unroll
    for (int k = 0; k < 4; ++k) {
        float dx = v[k].x - mu, dy = v[k].y - mu, dz = v[k].z - mu, dw = v[k].w - mu;
        vs += dx * dx + dy * dy + dz * dz + dw * dw;
    }
    #pragma unroll
    for (int o = 16; o > 0; o >>= 1) vs += __shfl_xor_sync(0xffffffffu, vs, o);
    float inv = rsqrtf(vs * (1.0f / C_) + 1e-5f);

    __half2* orow = (__half2*)(out + row * C_);
    #pragma unroll
    for (int k = 0; k < 4; ++k) {
        int i4 = lane + k * 32, c = i4 * 4;
        float e0 = (v[k].x - mu) * inv * sg[c]     + sb[c];
        float e1 = (v[k].y - mu) * inv * sg[c + 1] + sb[c + 1];
        float e2 = (v[k].z - mu) * inv * sg[c + 2] + sb[c + 2];
        float e3 = (v[k].w - mu) * inv * sg[c + 3] + sb[c + 3];
        orow[i4 * 2]     = __floats2half2_rn(e0, e1);
        orow[i4 * 2 + 1] = __floats2half2_rn(e2, e3);
    }
}

// ---------------- FP16 GEMM: 128x128 CTA, 4 warps, 64x64 warp tile ------------------
#define BM 128
#define BN 128
#define BKH 32
#define LST 40
#define STAGEH ((BM + BN) * LST)
#define GSMEM (3 * STAGEH * 2)

__device__ __forceinline__ void cpa16(uint32_t s, const void* g) {
    asm volatile("cp.async.ca.shared.global [%0], [%1], 16;" :: "r"(s), "l"(g));
}
__device__ __forceinline__ void ldsm4(uint32_t* r, uint32_t addr) {
    asm volatile("ldmatrix.sync.aligned.m8n8.x4.shared.b16 {%0,%1,%2,%3}, [%4];"
                 : "=r"(r[0]), "=r"(r[1]), "=r"(r[2]), "=r"(r[3]) : "r"(addr));
}
__device__ __forceinline__ void mma_f16(float* c, const uint32_t* a, const uint32_t* b) {
    asm volatile(
        "mma.sync.aligned.m16n8k16.row.col.f32.f16.f16.f32 "
        "{%0,%1,%2,%3}, {%4,%5,%6,%7}, {%8,%9}, {%0,%1,%2,%3};"
        : "+f"(c[0]), "+f"(c[1]), "+f"(c[2]), "+f"(c[3])
        : "r"(a[0]), "r"(a[1]), "r"(a[2]), "r"(a[3]), "r"(b[0]), "r"(b[1]));
}

template<bool OUT_HALF, bool HAS_RES>
__global__ __launch_bounds__(128, 2)
void gemm_h_kernel(const __half* __restrict__ A, const __half* __restrict__ Bm,
                   const float* __restrict__ bias, const float* __restrict__ res,
                   void* __restrict__ outv, int M, int N, int K) {
    extern __shared__ __half sm[];
    const uint32_t smb = (uint32_t)__cvta_generic_to_shared(sm);
    const int tid = threadIdx.x;
    const int lane = tid & 31, wid = tid >> 5;     // 4 warps
    const int wm = wid & 1, wn = wid >> 1;         // warp grid 2(M) x 2(N), tile 64x64
    const int g8 = lane >> 2, tig = lane & 3;
    const int m0 = blockIdx.y * BM, n0 = blockIdx.x * BN;

    float acc[4][8][4];
    #pragma unroll
    for (int i = 0; i < 4; ++i)
        #pragma unroll
        for (int j = 0; j < 8; ++j)
            #pragma unroll
            for (int t = 0; t < 4; ++t) acc[i][j][t] = 0.0f;

    const int T = K / BKH;
    const int lrow = tid >> 2, lq = tid & 3;       // 32 rows x 4 chunks per pass

    auto load_stage = [&](int t, int s) {
        const int k0 = t * BKH;
        #pragma unroll
        for (int i = 0; i < 4; ++i) {
            int row = lrow + i * 32;
            uint32_t sa = smb + (uint32_t)(s * STAGEH + row * LST + lq * 8) * 2u;
            cpa16(sa, A + (long)(m0 + row) * K + k0 + lq * 8);
            cpa16(sa + BM * LST * 2u, Bm + (long)(n0 + row) * K + k0 + lq * 8);
        }
    };

    load_stage(0, 0);
    asm volatile("cp.async.commit_group;");
    if (T > 1) { load_stage(1, 1); asm volatile("cp.async.commit_group;"); }

    const int a_r = (lane & 15), a_k = (lane >> 4) * 8;
    const int b_r = (lane & 7), b_t = (lane >> 4), b_k = ((lane >> 3) & 1) * 8;

    for (int t = 0; t < T; ++t) {
        const int s = t % 3;
        if (t + 2 < T) {
            load_stage(t + 2, (t + 2) % 3);
            asm volatile("cp.async.commit_group;");
            asm volatile("cp.async.wait_group 2;");
        } else if (t + 1 < T) {
            asm volatile("cp.async.wait_group 1;");
        } else {
            asm volatile("cp.async.wait_group 0;");
        }
        __syncthreads();

        const uint32_t sA = smb + (uint32_t)(s * STAGEH) * 2u;
        const uint32_t sB = sA + BM * LST * 2u;

        #pragma unroll
        for (int kk = 0; kk < 2; ++kk) {
            const int kb = kk * 16;
            uint32_t a[4][4], b[8][2];
            #pragma unroll
            for (int i = 0; i < 4; ++i)
                ldsm4(a[i], sA + (uint32_t)((wm * 64 + i * 16 + a_r) * LST + kb + a_k) * 2u);
            #pragma unroll
            for (int jp = 0; jp < 4; ++jp) {
                uint32_t r[4];
                ldsm4(r, sB + (uint32_t)((wn * 64 + (jp * 2 + b_t) * 8 + b_r) * LST + kb + b_k) * 2u);
                b[jp * 2][0] = r[0]; b[jp * 2][1] = r[1];
                b[jp * 2 + 1][0] = r[2]; b[jp * 2 + 1][1] = r[3];
            }
            #pragma unroll
            for (int i = 0; i < 4; ++i)
                #pragma unroll
                for (int j = 0; j < 8; ++j) mma_f16(acc[i][j], a[i], b[j]);
        }
        __syncthreads();
    }

    // epilogue
    #pragma unroll
    for (int i = 0; i < 4; ++i) {
        int r = m0 + wm * 64 + i * 16 + g8;
        #pragma unroll
        for (int j = 0; j < 8; ++j) {
            int n = n0 + wn * 64 + j * 8 + tig * 2;
            float b0 = bias[n], b1 = bias[n + 1];
            float v0 = acc[i][j][0] + b0, v1 = acc[i][j][1] + b1;
            float v2 = acc[i][j][2] + b0, v3 = acc[i][j][3] + b1;
            long o0 = (long)r * N + n;
            long o1 = (long)(r + 8) * N + n;
            if (HAS_RES) {
                float2 r0 = *(const float2*)(res + o0);
                float2 r1 = *(const float2*)(res + o1);
                v0 += r0.x; v1 += r0.y; v2 += r1.x; v3 += r1.y;
            }
            if (OUT_HALF) {
                __half* out = (__half*)outv;
                *(__half2*)(out + o0) = __floats2half2_rn(v0, v1);
                *(__half2*)(out + o1) = __floats2half2_rn(v2, v3);
            } else {
                float* out = (float*)outv;
                *(float2*)(out + o0) = make_float2(v0, v1);
                *(float2*)(out + o1) = make_float2(v2, v3);
            }
        }
    }
}

// ---------------- Windowed attention ----------------
__global__ __launch_bounds__(256)
void attn_kernel(const __half* __restrict__ qkv, const float* __restrict__ rpb,
                 const float* __restrict__ x, float* __restrict__ x1) {
    const int head = blockIdx.x & 15;
    const int win  = blockIdx.x >> 4;
    const int b    = win >> 6;
    const int wi   = (win >> 3) & 7;
    const int wj   = win & 7;
    const int tid  = threadIdx.x;

    __shared__ float q[WS2_][HD_ + 1];
    __shared__ float k[WS2_][HD_ + 1];
    __shared__ float v[WS2_][HD_ + 1];
    __shared__ float s[WS2_][WS2_ + 1];

    for (int idx = tid; idx < WS2_ * 16; idx += 256) {
        int p = idx >> 4, d2 = idx & 15;
        int token = (wi * 7 + p / 7) * 56 + (wj * 7 + p % 7);
        long base = ((long)b * N_ + token) * THREEC_ + head * HD_ + 2 * d2;
        float2 fq = __half22float2(*(const __half2*)(qkv + base));
        float2 fk = __half22float2(*(const __half2*)(qkv + base + C_));
        float2 fv = __half22float2(*(const __half2*)(qkv + base + 2 * C_));
        q[p][2 * d2] = fq.x; q[p][2 * d2 + 1] = fq.y;
        k[p][2 * d2] = fk.x; k[p][2 * d2 + 1] = fk.y;
        v[p][2 * d2] = fv.x; v[p][2 * d2 + 1] = fv.y;
    }
    __syncthreads();

    const float scale = 0.17677669529663687f;
    for (int idx = tid; idx < WS2_ * WS2_; idx += 256) {
        int i = idx / WS2_, j = idx - i * WS2_;
        float acc = 0.0f;
        #pragma unroll
        for (int d = 0; d < HD_; ++d) acc = fmaf(q[i][d], k[j][d], acc);
        int dpi = (i / 7) - (j / 7) + 6;
        int dpj = (i % 7) - (j % 7) + 6;
        s[i][j] = acc * scale + rpb[(dpi * 13 + dpj) * NH_ + head];
    }
    __syncthreads();

    if (tid < WS2_) {
        float mx = -1e30f;
        #pragma unroll
        for (int j = 0; j < WS2_; ++j) mx = fmaxf(mx, s[tid][j]);
        float sum = 0.0f;
        #pragma unroll
        for (int j = 0; j < WS2_; ++j) { float e = __expf(s[tid][j] - mx); s[tid][j] = e; sum += e; }
        float inv = 1.0f / sum;
        #pragma unroll
        for (int j = 0; j < WS2_; ++j) s[tid][j] *= inv;
    }
    __syncthreads();

    for (int idx = tid; idx < WS2_ * HD_; idx += 256) {
        int i = idx >> 5, d = idx & 31;
        float acc = 0.0f;
        #pragma unroll
        for (int j = 0; j < WS2_; ++j) acc = fmaf(s[i][j], v[j][d], acc);
        int token = (wi * 7 + i / 7) * 56 + (wj * 7 + i % 7);
        long o = ((long)b * N_ + token) * C_ + head * HD_ + d;
        x1[o] = x[o] + acc;
    }
}

// ---------------- depthwise 3x3 + GELU: row-sweep, sliding window --------------------
// One thread per (b, hrow, channel-pair); walks w=0..55 keeping the 3x3 window in regs.
__global__ __launch_bounds__(256)
void dwconv_gelu_kernel(const __half2* __restrict__ h2, const float* __restrict__ w,
                        const float* __restrict__ bias, __half2* __restrict__ out) {
    __shared__ float ws[512 * 9];
    const int bid = blockIdx.x;
    const int chunk = bid & 3;              // 4 chunks of 256 pairs
    const int hrow = (bid >> 2) % 56;
    const int bb = (bid >> 2) / 56;
    const int cp = chunk * 256 + threadIdx.x;

    for (int q = threadIdx.x; q < 512 * 9; q += 256)
        ws[q] = w[(long)(chunk * 512) * 9 + q];
    __syncthreads();

    const float* w0 = &ws[(2 * threadIdx.x) * 9];
    const float* w1 = w0 + 9;
    const int c = cp * 2;
    const float bi0 = bias[c], bi1 = bias[c + 1];

    const bool up = (hrow > 0), dn = (hrow < 55);
    const long rbase = (((long)bb * 56 + hrow) * 56) * 1024 + cp;   // half2 idx at w=0
    const long rup = rbase - 56 * 1024, rdn = rbase + 56 * 1024;

    // col[j][dy]: window columns; col index j in {0,1,2} -> w-1, w, w+1
    float2 col[3][3];
    #pragma unroll
    for (int j = 0; j < 3; ++j)
        #pragma unroll
        for (int dy = 0; dy < 3; ++dy) col[j][dy] = make_float2(0.f, 0.f);

    // preload column for w=0 into col[2] slot semantics: start with A(w-1)=0, B(w)=load(0)
    col[1][0] = up ? __half22float2(h2[rup]) : make_float2(0.f, 0.f);
    col[1][1] = __half22float2(h2[rbase]);
    col[1][2] = dn ? __half22float2(h2[rdn]) : make_float2(0.f, 0.f);

    for (int wcol = 0; wcol < 56; ++wcol) {
        if (wcol + 1 < 56) {
            long o = (long)(wcol + 1) * 1024;
            col[2][0] = up ? __half22float2(h2[rup + o]) : make_float2(0.f, 0.f);
            col[2][1] = __half22float2(h2[rbase + o]);
            col[2][2] = dn ? __half22float2(h2[rdn + o]) : make_float2(0.f, 0.f);
        } else {
            col[2][0] = col[2][1] = col[2][2] = make_float2(0.f, 0.f);
        }

        float a0 = bi0, a1 = bi1;
        #pragma unroll
        for (int dy = 0; dy < 3; ++dy) {
            #pragma unroll
            for (int dx = 0; dx < 3; ++dx) {
                float2 vv = col[dx][dy];
                a0 = fmaf(vv.x, w0[dy * 3 + dx], a0);
                a1 = fmaf(vv.y, w1[dy * 3 + dx], a1);
            }
        }
        float g0 = 0.5f * a0 * (1.0f + erff(a0 * 0.70710678118654752f));
        float g1 = 0.5f * a1 * (1.0f + erff(a1 * 0.70710678118654752f));
        out[rbase + (long)wcol * 1024] = __floats2half2_rn(g0, g1);

        #pragma unroll
        for (int dy = 0; dy < 3; ++dy) { col[0][dy] = col[1][dy]; col[1][dy] = col[2][dy]; }
    }
}

// ---------------- launch ----------------
extern "C" void kernel_launch(void* const* d_in, const int* in_sizes, int n_in,
                              void* d_out, int out_size) {
    const float* x       = (const float*)d_in[0];
    const float* norm1_g = (const float*)d_in[3];
    const float* norm1_b = (const float*)d_in[4];
    const float* norm2_g = (const float*)d_in[5];
    const float* norm2_b = (const float*)d_in[6];
    const float* qkv_w   = (const float*)d_in[7];
    const float* qkv_b   = (const float*)d_in[8];
    const float* rpb     = (const float*)d_in[9];
    const float* fc1_w   = (const float*)d_in[10];
    const float* fc1_b   = (const float*)d_in[11];
    const float* dw_w    = (const float*)d_in[12];
    const float* dw_b    = (const float*)d_in[13];
    const float* fc2_w   = (const float*)d_in[14];
    const float* fc2_b   = (const float*)d_in[15];
    float* out = (float*)d_out;

    __half *p_hh, *p_qkvh, *p_h2h, *p_h3h, *p_wq, *p_wf1, *p_wf2;
    float *p_x1;
    cudaGetSymbolAddress((void**)&p_hh,   g_hh);
    cudaGetSymbolAddress((void**)&p_qkvh, g_qkvh);
    cudaGetSymbolAddress((void**)&p_x1,   g_x1);
    cudaGetSymbolAddress((void**)&p_h2h,  g_h2h);
    cudaGetSymbolAddress((void**)&p_h3h,  g_h3h);
    cudaGetSymbolAddress((void**)&p_wq,   g_wq);
    cudaGetSymbolAddress((void**)&p_wf1,  g_wf1);
    cudaGetSymbolAddress((void**)&p_wf2,  g_wf2);

    cudaFuncSetAttribute(gemm_h_kernel<true, false>,
                         cudaFuncAttributeMaxDynamicSharedMemorySize, GSMEM);
    cudaFuncSetAttribute(gemm_h_kernel<false, true>,
                         cudaFuncAttributeMaxDynamicSharedMemorySize, GSMEM);

    // 0) weight conversions
    f2h_kernel<<<(THREEC_ * C_ / 4 + 255) / 256, 256>>>((const float4*)qkv_w, (__half2*)p_wq, THREEC_ * C_ / 4);
    f2h_kernel<<<(HID_ * C_ / 4 + 255) / 256, 256>>>((const float4*)fc1_w, (__half2*)p_wf1, HID_ * C_ / 4);
    f2h_kernel<<<(C_ * HID_ / 4 + 255) / 256, 256>>>((const float4*)fc2_w, (__half2*)p_wf2, C_ * HID_ / 4);

    // 1) LN1
    ln_kernel<<<TOK_ / 8, 256>>>(x, norm1_g, norm1_b, p_hh);
    // 2) QKV GEMM
    gemm_h_kernel<true, false><<<dim3(THREEC_ / BN, TOK_ / BM), 128, GSMEM>>>(
        p_hh, p_wq, qkv_b, nullptr, p_qkvh, TOK_, THREEC_, C_);
    // 3) windowed attention + residual
    attn_kernel<<<B_ * 64 * NH_, 256>>>(p_qkvh, rpb, x, p_x1);
    // 4) LN2
    ln_kernel<<<TOK_ / 8, 256>>>(p_x1, norm2_g, norm2_b, p_hh);
    // 5) fc1 GEMM
    gemm_h_kernel<true, false><<<dim3(HID_ / BN, TOK_ / BM), 128, GSMEM>>>(
        p_hh, p_wf1, fc1_b, nullptr, p_h2h, TOK_, HID_, C_);
    // 6) depthwise conv + GELU (row-sweep)
    dwconv_gelu_kernel<<<B_ * HH_ * 4, 256>>>(
        (const __half2*)p_h2h, dw_w, dw_b, (__half2*)p_h3h);
    // 7) fc2 GEMM + residual -> out
    gemm_h_kernel<false, true><<<dim3(C_ / BN, TOK_ / BM), 128, GSMEM>>>(
        p_h3h, p_wf2, fc2_b, p_x1, out, TOK_, C_, HID_);
}